// round 3
// baseline (speedup 1.0000x reference)
#include <cuda_runtime.h>
#include <math.h>

#define NN 100000
#define EE 1600000
#define HDIM 64

// ---------------- scratch (static device arrays; no allocation) -------------
__device__ float g_q[NN * HDIM];
__device__ float g_k[NN * HDIM];
__device__ float g_v[NN * HDIM];
__device__ float g_s[NN * HDIM];
__device__ int   g_off[NN + 1];

// ---------------- K1: fused projection GEMM  [N,64] @ [64,256] --------------
__global__ void proj_kernel(const float* __restrict__ feat,
                            const float* __restrict__ Wq, const float* __restrict__ bq,
                            const float* __restrict__ Wk, const float* __restrict__ bk,
                            const float* __restrict__ Wv, const float* __restrict__ bv,
                            const float* __restrict__ Ws, const float* __restrict__ bs)
{
    extern __shared__ float sm[];
    float* Wsm = sm;                 // 64*256
    float* fT  = sm + 64 * 256;      // 64*68 (transposed, padded)
    float* bsm = fT + 64 * 68;       // 256

    const int tid = threadIdx.x;

    for (int i = tid; i < 64 * 256; i += 256) {
        int kk = i >> 8, c = i & 255;
        int m = c >> 6, lc = c & 63;
        const float* W = (m == 0) ? Wq : (m == 1) ? Wk : (m == 2) ? Wv : Ws;
        Wsm[kk * 256 + c] = W[kk * 64 + lc];
    }
    {
        int c = tid, m = c >> 6, lc = c & 63;
        const float* b = (m == 0) ? bq : (m == 1) ? bk : (m == 2) ? bv : bs;
        bsm[c] = b[lc];
    }

    const int r0 = (tid >> 5) * 8;
    const int c0 = (tid & 31) * 8;
    const int mm = c0 >> 6, lc = c0 & 63;
    float* obase = (mm == 0) ? g_q : (mm == 1) ? g_k : (mm == 2) ? g_v : g_s;

    const int numTiles = (NN + 63) / 64;
    for (int tile = blockIdx.x; tile < numTiles; tile += gridDim.x) {
        const int rowbase = tile * 64;
        __syncthreads();
        for (int i = tid; i < 64 * 16; i += 256) {
            int r = i >> 4;
            int c4 = (i & 15) * 4;
            int row = rowbase + r;
            float4 vv = (row < NN) ? *(const float4*)&feat[row * 64 + c4]
                                   : make_float4(0.f, 0.f, 0.f, 0.f);
            fT[(c4 + 0) * 68 + r] = vv.x;
            fT[(c4 + 1) * 68 + r] = vv.y;
            fT[(c4 + 2) * 68 + r] = vv.z;
            fT[(c4 + 3) * 68 + r] = vv.w;
        }
        __syncthreads();

        float acc[64];
#pragma unroll
        for (int i = 0; i < 64; i++) acc[i] = 0.f;

#pragma unroll 8
        for (int kk = 0; kk < 64; kk++) {
            const float4 fa = *(const float4*)(fT + kk * 68 + r0);
            const float4 fb = *(const float4*)(fT + kk * 68 + r0 + 4);
            const float4 wa = *(const float4*)(Wsm + kk * 256 + c0);
            const float4 wb = *(const float4*)(Wsm + kk * 256 + c0 + 4);
            const float f[8] = {fa.x, fa.y, fa.z, fa.w, fb.x, fb.y, fb.z, fb.w};
            const float w[8] = {wa.x, wa.y, wa.z, wa.w, wb.x, wb.y, wb.z, wb.w};
#pragma unroll
            for (int i = 0; i < 8; i++)
#pragma unroll
                for (int j = 0; j < 8; j++)
                    acc[i * 8 + j] = fmaf(f[i], w[j], acc[i * 8 + j]);
        }

#pragma unroll
        for (int i = 0; i < 8; i++) {
            int row = rowbase + r0 + i;
            if (row < NN) {
                float4 o;
                o.x = acc[i * 8 + 0] + bsm[c0 + 0];
                o.y = acc[i * 8 + 1] + bsm[c0 + 1];
                o.z = acc[i * 8 + 2] + bsm[c0 + 2];
                o.w = acc[i * 8 + 3] + bsm[c0 + 3];
                *(float4*)&obase[row * 64 + lc] = o;
                o.x = acc[i * 8 + 4] + bsm[c0 + 4];
                o.y = acc[i * 8 + 5] + bsm[c0 + 5];
                o.z = acc[i * 8 + 6] + bsm[c0 + 6];
                o.w = acc[i * 8 + 7] + bsm[c0 + 7];
                *(float4*)&obase[row * 64 + lc + 4] = o;
            }
        }
    }
}

// ---------------- K2: CSR offsets via binary search on sorted edge_dst ------
__global__ void offsets_kernel(const int* __restrict__ dst)
{
    int n = blockIdx.x * blockDim.x + threadIdx.x;
    if (n > NN) return;
    if (n == NN) { g_off[NN] = EE; return; }
    int lo = 0, hi = EE;
    while (lo < hi) {
        int mid = (lo + hi) >> 1;
        if (dst[mid] < n) lo = mid + 1; else hi = mid;
    }
    g_off[n] = lo;
}

// ---------------- K3: fused edge attention + gate + LN + PReLU --------------
// one warp per destination node; lane l owns elements 2l, 2l+1 (head = l/8)
// 2 edges per iteration for MLP=2 on the gather loads.
__global__ void attn_kernel(const int* __restrict__ src_idx,
                            const float* __restrict__ Wg, const float* __restrict__ bg,
                            const float* __restrict__ ln_g, const float* __restrict__ ln_b,
                            const float* __restrict__ prelu_a,
                            float* __restrict__ out)
{
    const int warp = (blockIdx.x * blockDim.x + threadIdx.x) >> 5;
    const int lane = threadIdx.x & 31;
    if (warp >= NN) return;
    const int n = warp;
    const int e0 = lane * 2;

    const float2 kd = *(const float2*)&g_k[n * HDIM + e0];
    const int start = g_off[n];
    const int end   = g_off[n + 1];

    float m = -1e30f, s = 0.f, a0 = 0.f, a1 = 0.f;

    int e = start;
    for (; e + 2 <= end; e += 2) {
        const int srcA = __ldg(&src_idx[e]);
        const int srcB = __ldg(&src_idx[e + 1]);
        const float2 qA = *(const float2*)&g_q[srcA * HDIM + e0];
        const float2 qB = *(const float2*)&g_q[srcB * HDIM + e0];
        const float2 vA = *(const float2*)&g_v[srcA * HDIM + e0];
        const float2 vB = *(const float2*)&g_v[srcB * HDIM + e0];

        float pA = qA.x * kd.x + qA.y * kd.y;
        float pB = qB.x * kd.x + qB.y * kd.y;
        pA += __shfl_xor_sync(0xffffffffu, pA, 1);
        pB += __shfl_xor_sync(0xffffffffu, pB, 1);
        pA += __shfl_xor_sync(0xffffffffu, pA, 2);
        pB += __shfl_xor_sync(0xffffffffu, pB, 2);
        pA += __shfl_xor_sync(0xffffffffu, pA, 4);
        pB += __shfl_xor_sync(0xffffffffu, pB, 4);
        const float sA = pA * 0.25f;   // 1/sqrt(16)
        const float sB = pB * 0.25f;

        const float nm = fmaxf(m, fmaxf(sA, sB));
        const float sc = __expf(m - nm);
        const float eA = __expf(sA - nm);
        const float eB = __expf(sB - nm);
        s  = s  * sc + eA + eB;
        a0 = a0 * sc + eA * vA.x + eB * vB.x;
        a1 = a1 * sc + eA * vA.y + eB * vB.y;
        m = nm;
    }
    if (e < end) {
        const int src = __ldg(&src_idx[e]);
        const float2 qs = *(const float2*)&g_q[src * HDIM + e0];
        const float2 vs = *(const float2*)&g_v[src * HDIM + e0];
        float p = qs.x * kd.x + qs.y * kd.y;
        p += __shfl_xor_sync(0xffffffffu, p, 1);
        p += __shfl_xor_sync(0xffffffffu, p, 2);
        p += __shfl_xor_sync(0xffffffffu, p, 4);
        const float score = p * 0.25f;
        const float nm = fmaxf(m, score);
        const float sc = __expf(m - nm);
        const float pe = __expf(score - nm);
        s  = s  * sc + pe;
        a0 = a0 * sc + pe * vs.x;
        a1 = a1 * sc + pe * vs.y;
        m = nm;
    }

    if (end > start) {
        const float inv = 1.f / s;
        a0 *= inv; a1 *= inv;
    } else {
        a0 = 0.f; a1 = 0.f;
    }

    // gated skip: gate = sigmoid([skip, rst, skip-rst] @ Wg + bg)
    const float2 sk = *(const float2*)&g_s[n * HDIM + e0];
    float gd = sk.x * Wg[e0] + sk.y * Wg[e0 + 1]
             + a0 * Wg[64 + e0] + a1 * Wg[64 + e0 + 1]
             + (sk.x - a0) * Wg[128 + e0] + (sk.y - a1) * Wg[128 + e0 + 1];
    gd += __shfl_xor_sync(0xffffffffu, gd, 1);
    gd += __shfl_xor_sync(0xffffffffu, gd, 2);
    gd += __shfl_xor_sync(0xffffffffu, gd, 4);
    gd += __shfl_xor_sync(0xffffffffu, gd, 8);
    gd += __shfl_xor_sync(0xffffffffu, gd, 16);
    const float gate = 1.f / (1.f + __expf(-(gd + bg[0])));

    float r0v = gate * sk.x + (1.f - gate) * a0;
    float r1v = gate * sk.y + (1.f - gate) * a1;

    // layer norm over 64
    float msum = r0v + r1v;
    msum += __shfl_xor_sync(0xffffffffu, msum, 1);
    msum += __shfl_xor_sync(0xffffffffu, msum, 2);
    msum += __shfl_xor_sync(0xffffffffu, msum, 4);
    msum += __shfl_xor_sync(0xffffffffu, msum, 8);
    msum += __shfl_xor_sync(0xffffffffu, msum, 16);
    const float mu = msum * (1.f / 64.f);
    const float dx = r0v - mu, dy = r1v - mu;
    float vsum = dx * dx + dy * dy;
    vsum += __shfl_xor_sync(0xffffffffu, vsum, 1);
    vsum += __shfl_xor_sync(0xffffffffu, vsum, 2);
    vsum += __shfl_xor_sync(0xffffffffu, vsum, 4);
    vsum += __shfl_xor_sync(0xffffffffu, vsum, 8);
    vsum += __shfl_xor_sync(0xffffffffu, vsum, 16);
    const float var = vsum * (1.f / 64.f);
    const float rstd = rsqrtf(var + 1e-5f);

    float y0 = dx * rstd * ln_g[e0]     + ln_b[e0];
    float y1 = dy * rstd * ln_g[e0 + 1] + ln_b[e0 + 1];

    const float alpha = prelu_a[0];
    y0 = (y0 >= 0.f) ? y0 : alpha * y0;
    y1 = (y1 >= 0.f) ? y1 : alpha * y1;

    float2 o; o.x = y0; o.y = y1;
    *(float2*)&out[n * HDIM + e0] = o;
}

// ---------------- launch -----------------------------------------------------
extern "C" void kernel_launch(void* const* d_in, const int* in_sizes, int n_in,
                              void* d_out, int out_size)
{
    const float* feat   = (const float*)d_in[0];
    const int*   esrc   = (const int*)d_in[1];
    const int*   edst   = (const int*)d_in[2];
    const float* Wq     = (const float*)d_in[3];
    const float* bq     = (const float*)d_in[4];
    const float* Wk     = (const float*)d_in[5];
    const float* bk     = (const float*)d_in[6];
    const float* Wv     = (const float*)d_in[7];
    const float* bv     = (const float*)d_in[8];
    const float* Ws     = (const float*)d_in[9];
    const float* bs     = (const float*)d_in[10];
    const float* Wg     = (const float*)d_in[11];
    const float* bg     = (const float*)d_in[12];
    const float* ln_g   = (const float*)d_in[13];
    const float* ln_b   = (const float*)d_in[14];
    const float* pa     = (const float*)d_in[15];
    float* out = (float*)d_out;

    const int smem = (64 * 256 + 64 * 68 + 256) * sizeof(float); // 83968 B
    cudaFuncSetAttribute(proj_kernel, cudaFuncAttributeMaxDynamicSharedMemorySize, smem);

    proj_kernel<<<296, 256, smem>>>(feat, Wq, bq, Wk, bk, Wv, bv, Ws, bs);
    offsets_kernel<<<(NN + 1 + 255) / 256, 256>>>(edst);
    attn_kernel<<<(NN + 7) / 8, 256>>>(esrc, Wg, bg, ln_g, ln_b, pa, out);
}